// round 14
// baseline (speedup 1.0000x reference)
#include <cuda_runtime.h>
#include <cuda_bf16.h>
#include <cstdint>

#define DD 128
#define MAXN 100000
#define PK 136            // smem tile pitch in bf16 halves (conflict-free for ldmatrix)

// ---------------- scratch (__device__ globals; no allocs allowed) ----------------
__device__ float g_agg[2][(size_t)MAXN * DD];   // double-buffered (one merged memset)
__device__ float g_h[(size_t)MAXN * DD];
__device__ float g_deg[MAXN];
// bf16 hi/lo images of B = [W;Wloop]^T, row-major [n=128][k=256]:
// index l*2+0 = hi, l*2+1 = lo, per layer l.
__device__ __align__(16) __nv_bfloat16 g_B[4][32768];

__device__ __forceinline__ uint32_t smem_u32(const void* p) {
    uint32_t a;
    asm("{ .reg .u64 t; cvta.to.shared.u64 t, %1; cvt.u32.u64 %0, t; }" : "=r"(a) : "l"(p));
    return a;
}
__device__ __forceinline__ float tanh_fast(float v) {
    float r;
    asm("tanh.approx.f32 %0, %1;" : "=f"(r) : "f"(v));
    return r;
}
#define LDSM_X4(R, addr) \
    asm volatile("ldmatrix.sync.aligned.m8n8.x4.shared.b16 {%0,%1,%2,%3}, [%4];" \
        : "=r"((R)[0]), "=r"((R)[1]), "=r"((R)[2]), "=r"((R)[3]) : "r"(addr))

__device__ __forceinline__ void mma_bf16(float* c, const uint32_t* a, uint32_t b0, uint32_t b1) {
    asm volatile(
        "mma.sync.aligned.m16n8k16.row.col.f32.bf16.bf16.f32 "
        "{%0,%1,%2,%3}, {%4,%5,%6,%7}, {%8,%9}, {%0,%1,%2,%3};"
        : "+f"(c[0]), "+f"(c[1]), "+f"(c[2]), "+f"(c[3])
        : "r"(a[0]), "r"(a[1]), "r"(a[2]), "r"(a[3]), "r"(b0), "r"(b1));
}

// ---------------------------------------------------------------------------
// Prep: B[n][k] = (k<128 ? W[k][n] : Wl[k-128][n]); hi/lo bf16 split, row-major.
// ---------------------------------------------------------------------------
__global__ void prep_kernel(const float* __restrict__ W1, const float* __restrict__ Wl1,
                            const float* __restrict__ W2, const float* __restrict__ Wl2) {
    int idx = blockIdx.x * blockDim.x + threadIdx.x;   // 0..65535
    int l = idx >> 15;
    int n = (idx >> 8) & 127;
    int k = idx & 255;
    const float* W  = l ? W2  : W1;
    const float* Wl = l ? Wl2 : Wl1;
    float v = (k < 128) ? W[k * 128 + n] : Wl[(k - 128) * 128 + n];
    __nv_bfloat16 hi = __float2bfloat16(v);
    __nv_bfloat16 lo = __float2bfloat16(v - __bfloat162float(hi));
    g_B[l * 2 + 0][n * 256 + k] = hi;
    g_B[l * 2 + 1][n * 256 + k] = lo;
}

// ---------------------------------------------------------------------------
// Scatter (persistent, rel cached in smem): agg[dst] += x[src] * rel[type].
// 296 blocks x 256 thr, grid-stride, 4 edges per warp per iter.
// ---------------------------------------------------------------------------
__global__ void __launch_bounds__(256, 2) scatter_kernel(
    const float* __restrict__ x, const float* __restrict__ rel,
    const int* __restrict__ ei, const int* __restrict__ et,
    int E, int R, float* __restrict__ agg, float* __restrict__ deg)
{
    extern __shared__ float srel[];          // R * 128 floats
    for (int i = threadIdx.x; i < R * 32; i += blockDim.x)
        ((float4*)srel)[i] = __ldg(((const float4*)rel) + i);
    __syncthreads();

    int lane = threadIdx.x & 31;
    int gw   = (blockIdx.x * blockDim.x + threadIdx.x) >> 5;
    int nw   = (gridDim.x * blockDim.x) >> 5;

    for (int e0 = gw * 4; e0 < E; e0 += nw * 4) {
        int  sidx[4], didx[4], tidx[4];
        bool ok[4];
        #pragma unroll
        for (int q = 0; q < 4; q++) {
            int e = e0 + q;
            ok[q] = e < E;
            int es = ok[q] ? e : e0;
            sidx[q] = __ldg(ei + es);
            didx[q] = __ldg(ei + E + es);
            tidx[q] = __ldg(et + es);
        }
        float4 xv[4];
        #pragma unroll
        for (int q = 0; q < 4; q++)
            xv[q] = *(const float4*)(x + (size_t)sidx[q] * DD + lane * 4);
        #pragma unroll
        for (int q = 0; q < 4; q++) {
            if (ok[q]) {
                float4 rv = *(const float4*)(srel + tidx[q] * DD + lane * 4);
                float4 m = make_float4(xv[q].x * rv.x, xv[q].y * rv.y,
                                       xv[q].z * rv.z, xv[q].w * rv.w);
                atomicAdd((float4*)(agg + (size_t)didx[q] * DD + lane * 4), m);
            }
        }
        if (deg != nullptr && lane == 0) {
            #pragma unroll
            for (int q = 0; q < 4; q++)
                if (ok[q]) atomicAdd(deg + didx[q], 1.0f);
        }
    }
}

// ---------------------------------------------------------------------------
// Jump: out[jdst] += jump_weight * edge_w * emb[jsrc]; 4 edges per warp.
// ---------------------------------------------------------------------------
__global__ void jump_kernel(const float* __restrict__ emb, const float* __restrict__ ew,
                            const int* __restrict__ ej, const float* __restrict__ jw,
                            int EJ, float* __restrict__ out) {
    int gw   = (blockIdx.x * blockDim.x + threadIdx.x) >> 5;
    int lane = threadIdx.x & 31;
    int e0 = gw * 4;
    if (e0 >= EJ) return;
    float jwv = jw[0];
    int  sidx[4], didx[4];
    bool ok[4];
    float wq[4];
    #pragma unroll
    for (int q = 0; q < 4; q++) {
        int e = e0 + q;
        ok[q] = e < EJ;
        int es = ok[q] ? e : e0;
        sidx[q] = __ldg(ej + es);
        didx[q] = __ldg(ej + EJ + es);
        wq[q]   = jwv * __ldg(ew + es);
    }
    float4 xv[4];
    #pragma unroll
    for (int q = 0; q < 4; q++)
        xv[q] = *(const float4*)(emb + (size_t)sidx[q] * DD + lane * 4);
    #pragma unroll
    for (int q = 0; q < 4; q++) {
        if (ok[q]) {
            float4 m = make_float4(wq[q] * xv[q].x, wq[q] * xv[q].y,
                                   wq[q] * xv[q].z, wq[q] * xv[q].w);
            atomicAdd((float4*)(out + (size_t)didx[q] * DD + lane * 4), m);
        }
    }
}

// ---------------------------------------------------------------------------
// Combine (HMMA, 2-term split): out[n] = x[n] + res*tanh([agg/deg | x] @ [W;Wl])
// CTA: 64 nodes x 128 outs, K=256 in two 128-halves. 8 warps as 2(M) x 4(N).
// Terms: Ah*Bh + Ah*Bl (A-rounding error ~1e-4 at output, within tolerance).
// smem: Ah (17KB) + Bh,Bl (70KB) = 87KB -> 2 CTAs/SM.
// ---------------------------------------------------------------------------
__global__ void __launch_bounds__(256, 2) combine_hmma(
    const float* __restrict__ agg, const float* __restrict__ deg,
    const float* __restrict__ x,
    const __nv_bfloat16* __restrict__ Bhi, const __nv_bfloat16* __restrict__ Blo,
    const float* __restrict__ resp, float* __restrict__ out, int N)
{
    extern __shared__ char smem[];
    const int TILE_A = 64 * PK * 2;                  // 17408 B
    const int TILE_B = 128 * PK * 2;                 // 34816 B
    const int OF_AH = 0, OF_BH = TILE_A, OF_BL = TILE_A + TILE_B;
    const uint32_t sb = smem_u32(smem);

    int tid = threadIdx.x, wid = tid >> 5, lane = tid & 31;
    int n0 = blockIdx.x * 64;
    int wn = wid & 3, wm = wid >> 2;                 // 4 N-groups x 2 M-groups

    int lrow = (lane & 7) + ((lane >> 3) & 1) * 8;
    int lcol = ((lane >> 4) & 1) * 8;

    uint32_t aoffs[2], boffs[2];
    #pragma unroll
    for (int mi = 0; mi < 2; mi++)
        aoffs[mi] = (uint32_t)(((wm * 32 + mi * 16 + lrow) * PK + lcol) * 2);
    #pragma unroll
    for (int bj = 0; bj < 2; bj++)
        boffs[bj] = (uint32_t)(((wn * 32 + bj * 16 + lrow) * PK + lcol) * 2);

    float acc[2][4][4];
    #pragma unroll
    for (int mi = 0; mi < 2; mi++)
        #pragma unroll
        for (int j = 0; j < 4; j++)
            #pragma unroll
            for (int q = 0; q < 4; q++) acc[mi][j][q] = 0.0f;

    for (int half = 0; half < 2; half++) {
        if (half) __syncthreads();

        // --- A half: 64 rows x 128-k slice (agg/deg or x), hi only
        const float* src = half ? x : agg;
        for (int i = tid; i < 64 * 32; i += 256) {
            int row = i >> 5, c4 = i & 31, node = n0 + row;
            float4 v = make_float4(0, 0, 0, 0);
            if (node < N) {
                v = ((const float4*)(src + (size_t)node * DD))[c4];
                if (half == 0) {
                    float sc = 1.0f / fmaxf(deg[node], 1.0f);
                    v.x *= sc; v.y *= sc; v.z *= sc; v.w *= sc;
                }
            }
            unsigned long long hp =
                (unsigned long long)__bfloat16_as_ushort(__float2bfloat16(v.x)) |
                ((unsigned long long)__bfloat16_as_ushort(__float2bfloat16(v.y)) << 16) |
                ((unsigned long long)__bfloat16_as_ushort(__float2bfloat16(v.z)) << 32) |
                ((unsigned long long)__bfloat16_as_ushort(__float2bfloat16(v.w)) << 48);
            *(unsigned long long*)(smem + OF_AH + (size_t)(row * PK + c4 * 4) * 2) = hp;
        }
        // --- B half: [128 n][128 k-slice] from prebuilt images (pure copy)
        const uint4* bh = (const uint4*)(Bhi + half * 128);
        const uint4* bl = (const uint4*)(Blo + half * 128);
        for (int i = tid; i < 128 * 16; i += 256) {
            int row = i >> 4, c = i & 15;
            uint4 vh = bh[row * 32 + c];
            uint4 vl = bl[row * 32 + c];
            size_t doff = (size_t)row * PK * 2 + (size_t)c * 16;
            *(uint4*)(smem + OF_BH + doff) = vh;
            *(uint4*)(smem + OF_BL + doff) = vl;
        }
        __syncthreads();

        // --- MMA over 8 k16 steps: Ah*Bh + Ah*Bl
        #pragma unroll
        for (int s = 0; s < 8; s++) {
            uint32_t kb = (uint32_t)s * 32;
            uint32_t ah[2][4];
            #pragma unroll
            for (int mi = 0; mi < 2; mi++)
                LDSM_X4(ah[mi], sb + OF_AH + aoffs[mi] + kb);
            #pragma unroll
            for (int bj = 0; bj < 2; bj++) {
                uint32_t bhf[4], blf[4];
                LDSM_X4(bhf, sb + OF_BH + boffs[bj] + kb);
                LDSM_X4(blf, sb + OF_BL + boffs[bj] + kb);
                #pragma unroll
                for (int mi = 0; mi < 2; mi++) {
                    mma_bf16(acc[mi][bj * 2 + 0], ah[mi], bhf[0], bhf[2]);
                    mma_bf16(acc[mi][bj * 2 + 0], ah[mi], blf[0], blf[2]);
                    mma_bf16(acc[mi][bj * 2 + 1], ah[mi], bhf[1], bhf[3]);
                    mma_bf16(acc[mi][bj * 2 + 1], ah[mi], blf[1], blf[3]);
                }
            }
        }
    }

    // --- epilogue: warp covers rows wm*32..+31, cols wn*32..+31
    float res = resp[0];
    int rbase = n0 + wm * 32 + (lane >> 2);
    int cbase = wn * 32 + (lane & 3) * 2;
    #pragma unroll
    for (int mi = 0; mi < 2; mi++) {
        #pragma unroll
        for (int j = 0; j < 4; j++) {
            int col = cbase + j * 8;
            int nlo = rbase + mi * 16;
            int nhi = nlo + 8;
            if (nlo < N) {
                const float2 xv = *(const float2*)(x + (size_t)nlo * DD + col);
                float2 o;
                o.x = xv.x + res * tanh_fast(acc[mi][j][0]);
                o.y = xv.y + res * tanh_fast(acc[mi][j][1]);
                *(float2*)(out + (size_t)nlo * DD + col) = o;
            }
            if (nhi < N) {
                const float2 xv = *(const float2*)(x + (size_t)nhi * DD + col);
                float2 o;
                o.x = xv.x + res * tanh_fast(acc[mi][j][2]);
                o.y = xv.y + res * tanh_fast(acc[mi][j][3]);
                *(float2*)(out + (size_t)nhi * DD + col) = o;
            }
        }
    }
}

// ---------------------------------------------------------------------------
// Launch
// ---------------------------------------------------------------------------
extern "C" void kernel_launch(void* const* d_in, const int* in_sizes, int n_in,
                              void* d_out, int out_size) {
    const float* emb    = (const float*)d_in[0];
    const float* change = (const float*)d_in[1];
    const float* W1     = (const float*)d_in[2];
    const float* Wl1    = (const float*)d_in[3];
    const float* rel1   = (const float*)d_in[4];
    const float* W2     = (const float*)d_in[5];
    const float* Wl2    = (const float*)d_in[6];
    const float* rel2   = (const float*)d_in[7];
    const float* res    = (const float*)d_in[8];
    const float* jw     = (const float*)d_in[9];
    const float* ewj    = (const float*)d_in[10];
    const int*   ei     = (const int*)d_in[11];
    const int*   et     = (const int*)d_in[12];
    const int*   ej     = (const int*)d_in[13];

    int N  = in_sizes[0] / DD;       // 100000
    int R  = in_sizes[4] / DD;       // 200
    int E  = in_sizes[12];           // 600000
    int EJ = in_sizes[10];           // 300000

    float* out1 = (float*)d_out;
    float* out2 = out1 + (size_t)N * DD;

    float *aggbase, *h, *deg;
    __nv_bfloat16 (*B)[32768];
    cudaGetSymbolAddress((void**)&aggbase, g_agg);
    cudaGetSymbolAddress((void**)&h,   g_h);
    cudaGetSymbolAddress((void**)&deg, g_deg);
    cudaGetSymbolAddress((void**)&B,   g_B);
    float* agg0 = aggbase;
    float* agg1 = aggbase + (size_t)MAXN * DD;

    const int SMEM_C = 64 * PK * 2 + 2 * 128 * PK * 2;   // 87040 B
    cudaFuncSetAttribute(combine_hmma, cudaFuncAttributeMaxDynamicSharedMemorySize, SMEM_C);
    const int SMEM_S = R * DD * (int)sizeof(float);      // 102400 B
    cudaFuncSetAttribute(scatter_kernel, cudaFuncAttributeMaxDynamicSharedMemorySize, SMEM_S);

    size_t fbytes = (size_t)N * DD * sizeof(float);
    long long jwarps = (EJ + 3) / 4;
    int jblocks = (int)((jwarps * 32 + 255) / 256);
    int cblocks = (N + 63) / 64;
    int sblocks = 296;                                   // persistent: 2 per SM

    prep_kernel<<<256, 256>>>(W1, Wl1, W2, Wl2);
    cudaMemsetAsync(aggbase, 0, 2 * fbytes, 0);          // both agg buffers at once
    cudaMemsetAsync(deg, 0, (size_t)N * sizeof(float), 0);

    // Layer 1 (degree fused into scatter)
    scatter_kernel<<<sblocks, 256, SMEM_S>>>(emb, rel1, ei, et, E, R, agg0, deg);
    combine_hmma<<<cblocks, 256, SMEM_C>>>(agg0, deg, emb, B[0], B[1], res, h, N);

    // Layer 2 (writes directly into out2)
    scatter_kernel<<<sblocks, 256, SMEM_S>>>(h, rel2, ei, et, E, R, agg1, nullptr);
    combine_hmma<<<cblocks, 256, SMEM_C>>>(agg1, deg, h, B[2], B[3], res, out2, N);

    // Jump diffusion accumulates into out2; change passthrough into out1
    jump_kernel<<<jblocks, 256>>>(emb, ewj, ej, jw, EJ, out2);
    cudaMemcpyAsync(out1, change, fbytes, cudaMemcpyDeviceToDevice, 0);
}

// round 15
// speedup vs baseline: 1.3607x; 1.3607x over previous
#include <cuda_runtime.h>
#include <cuda_fp16.h>
#include <cstdint>

#define DD 128
#define MAXN 100000
#define PK 136            // smem tile pitch in fp16 halves (conflict-free for ldmatrix)

// ---------------- scratch (__device__ globals; no allocs allowed) ----------------
__device__ float g_agg[2][(size_t)MAXN * DD];   // double-buffered (one merged memset)
__device__ float g_h[(size_t)MAXN * DD];
__device__ float g_deg[MAXN];
// fp16 images of B = [W;Wloop]^T, row-major [n=128][k=256], one per layer.
__device__ __align__(16) __half g_B[2][32768];

__device__ __forceinline__ uint32_t smem_u32(const void* p) {
    uint32_t a;
    asm("{ .reg .u64 t; cvta.to.shared.u64 t, %1; cvt.u32.u64 %0, t; }" : "=r"(a) : "l"(p));
    return a;
}
__device__ __forceinline__ float tanh_fast(float v) {
    float r;
    asm("tanh.approx.f32 %0, %1;" : "=f"(r) : "f"(v));
    return r;
}
#define LDSM_X4(R, addr) \
    asm volatile("ldmatrix.sync.aligned.m8n8.x4.shared.b16 {%0,%1,%2,%3}, [%4];" \
        : "=r"((R)[0]), "=r"((R)[1]), "=r"((R)[2]), "=r"((R)[3]) : "r"(addr))

__device__ __forceinline__ void mma_fp16(float* c, const uint32_t* a, uint32_t b0, uint32_t b1) {
    asm volatile(
        "mma.sync.aligned.m16n8k16.row.col.f32.f16.f16.f32 "
        "{%0,%1,%2,%3}, {%4,%5,%6,%7}, {%8,%9}, {%0,%1,%2,%3};"
        : "+f"(c[0]), "+f"(c[1]), "+f"(c[2]), "+f"(c[3])
        : "r"(a[0]), "r"(a[1]), "r"(a[2]), "r"(a[3]), "r"(b0), "r"(b1));
}

// ---------------------------------------------------------------------------
// Prep: B[n][k] = (k<128 ? W[k][n] : Wl[k-128][n]); fp16, row-major.
// ---------------------------------------------------------------------------
__global__ void prep_kernel(const float* __restrict__ W1, const float* __restrict__ Wl1,
                            const float* __restrict__ W2, const float* __restrict__ Wl2) {
    int idx = blockIdx.x * blockDim.x + threadIdx.x;   // 0..65535
    int l = idx >> 15;
    int n = (idx >> 8) & 127;
    int k = idx & 255;
    const float* W  = l ? W2  : W1;
    const float* Wl = l ? Wl2 : Wl1;
    float v = (k < 128) ? W[k * 128 + n] : Wl[(k - 128) * 128 + n];
    g_B[l][n * 256 + k] = __float2half_rn(v);
}

// ---------------------------------------------------------------------------
// Scatter: agg[dst] += x[src] * rel[type]; 4 edges per warp (MLP), optional degree.
// (R13 version — fastest measured: 64 us)
// ---------------------------------------------------------------------------
__global__ void scatter_kernel(const float* __restrict__ x, const float* __restrict__ rel,
                               const int* __restrict__ ei, const int* __restrict__ et,
                               int E, float* __restrict__ agg, float* __restrict__ deg) {
    int gw   = (blockIdx.x * blockDim.x + threadIdx.x) >> 5;
    int lane = threadIdx.x & 31;
    int e0 = gw * 4;
    if (e0 >= E) return;
    int   sidx[4], didx[4], tidx[4];
    bool  ok[4];
    #pragma unroll
    for (int q = 0; q < 4; q++) {
        int e = e0 + q;
        ok[q] = e < E;
        int es = ok[q] ? e : e0;
        sidx[q] = __ldg(ei + es);
        didx[q] = __ldg(ei + E + es);
        tidx[q] = __ldg(et + es);
    }
    float4 xv[4], rv[4];
    #pragma unroll
    for (int q = 0; q < 4; q++) {
        xv[q] = *(const float4*)(x + (size_t)sidx[q] * DD + lane * 4);
        rv[q] = __ldg((const float4*)(rel + (size_t)tidx[q] * DD + lane * 4));
    }
    #pragma unroll
    for (int q = 0; q < 4; q++) {
        if (ok[q]) {
            float4 m = make_float4(xv[q].x * rv[q].x, xv[q].y * rv[q].y,
                                   xv[q].z * rv[q].z, xv[q].w * rv[q].w);
            atomicAdd((float4*)(agg + (size_t)didx[q] * DD + lane * 4), m);
        }
    }
    if (deg != nullptr && lane == 0) {
        #pragma unroll
        for (int q = 0; q < 4; q++)
            if (ok[q]) atomicAdd(deg + didx[q], 1.0f);
    }
}

// ---------------------------------------------------------------------------
// Jump: out[jdst] += jump_weight * edge_w * emb[jsrc]; 4 edges per warp.
// ---------------------------------------------------------------------------
__global__ void jump_kernel(const float* __restrict__ emb, const float* __restrict__ ew,
                            const int* __restrict__ ej, const float* __restrict__ jw,
                            int EJ, float* __restrict__ out) {
    int gw   = (blockIdx.x * blockDim.x + threadIdx.x) >> 5;
    int lane = threadIdx.x & 31;
    int e0 = gw * 4;
    if (e0 >= EJ) return;
    float jwv = jw[0];
    int  sidx[4], didx[4];
    bool ok[4];
    float wq[4];
    #pragma unroll
    for (int q = 0; q < 4; q++) {
        int e = e0 + q;
        ok[q] = e < EJ;
        int es = ok[q] ? e : e0;
        sidx[q] = __ldg(ej + es);
        didx[q] = __ldg(ej + EJ + es);
        wq[q]   = jwv * __ldg(ew + es);
    }
    float4 xv[4];
    #pragma unroll
    for (int q = 0; q < 4; q++)
        xv[q] = *(const float4*)(emb + (size_t)sidx[q] * DD + lane * 4);
    #pragma unroll
    for (int q = 0; q < 4; q++) {
        if (ok[q]) {
            float4 m = make_float4(wq[q] * xv[q].x, wq[q] * xv[q].y,
                                   wq[q] * xv[q].z, wq[q] * xv[q].w);
            atomicAdd((float4*)(out + (size_t)didx[q] * DD + lane * 4), m);
        }
    }
}

// ---------------------------------------------------------------------------
// Combine (fp16 HMMA): out[n] = x[n] + res*tanh([agg/deg | x] @ [W;Wl])
// CTA: 64 nodes x 128 outs, K=256 in two 128-halves. 8 warps as 2(M) x 4(N).
// fp16 inputs, fp32 accum — data range fits fp16; rounding ~1e-4 at output.
// smem: A (17KB) + B (35KB) = 52KB -> 3 CTAs/SM.
// ---------------------------------------------------------------------------
__global__ void __launch_bounds__(256, 3) combine_hmma(
    const float* __restrict__ agg, const float* __restrict__ deg,
    const float* __restrict__ x,
    const __half* __restrict__ Bimg,
    const float* __restrict__ resp, float* __restrict__ out, int N)
{
    extern __shared__ char smem[];
    const int TILE_A = 64 * PK * 2;                  // 17408 B
    const int OF_A = 0, OF_B = TILE_A;
    const uint32_t sb = smem_u32(smem);

    int tid = threadIdx.x, wid = tid >> 5, lane = tid & 31;
    int n0 = blockIdx.x * 64;
    int wn = wid & 3, wm = wid >> 2;                 // 4 N-groups x 2 M-groups

    int lrow = (lane & 7) + ((lane >> 3) & 1) * 8;
    int lcol = ((lane >> 4) & 1) * 8;

    uint32_t aoffs[2], boffs[2];
    #pragma unroll
    for (int mi = 0; mi < 2; mi++)
        aoffs[mi] = (uint32_t)(((wm * 32 + mi * 16 + lrow) * PK + lcol) * 2);
    #pragma unroll
    for (int bj = 0; bj < 2; bj++)
        boffs[bj] = (uint32_t)(((wn * 32 + bj * 16 + lrow) * PK + lcol) * 2);

    float acc[2][4][4];
    #pragma unroll
    for (int mi = 0; mi < 2; mi++)
        #pragma unroll
        for (int j = 0; j < 4; j++)
            #pragma unroll
            for (int q = 0; q < 4; q++) acc[mi][j][q] = 0.0f;

    for (int half = 0; half < 2; half++) {
        if (half) __syncthreads();

        // --- A half: 64 rows x 128-k slice (agg/deg or x) -> fp16
        const float* src = half ? x : agg;
        for (int i = tid; i < 64 * 32; i += 256) {
            int row = i >> 5, c4 = i & 31, node = n0 + row;
            float4 v = make_float4(0, 0, 0, 0);
            if (node < N) {
                v = ((const float4*)(src + (size_t)node * DD))[c4];
                if (half == 0) {
                    float sc = 1.0f / fmaxf(deg[node], 1.0f);
                    v.x *= sc; v.y *= sc; v.z *= sc; v.w *= sc;
                }
            }
            __half2 p0 = __floats2half2_rn(v.x, v.y);
            __half2 p1 = __floats2half2_rn(v.z, v.w);
            unsigned long long hp =
                (unsigned long long)(*(const unsigned*)&p0) |
                ((unsigned long long)(*(const unsigned*)&p1) << 32);
            *(unsigned long long*)(smem + OF_A + (size_t)(row * PK + c4 * 4) * 2) = hp;
        }
        // --- B half: [128 n][128 k-slice] from prebuilt image (pure copy)
        const uint4* bi = (const uint4*)(Bimg + half * 128);
        for (int i = tid; i < 128 * 16; i += 256) {
            int row = i >> 4, c = i & 15;
            uint4 vh = bi[row * 32 + c];
            *(uint4*)(smem + OF_B + (size_t)row * PK * 2 + (size_t)c * 16) = vh;
        }
        __syncthreads();

        // --- MMA over 8 k16 steps
        #pragma unroll
        for (int s = 0; s < 8; s++) {
            uint32_t kb = (uint32_t)s * 32;
            uint32_t ah[2][4];
            #pragma unroll
            for (int mi = 0; mi < 2; mi++)
                LDSM_X4(ah[mi], sb + OF_A + aoffs[mi] + kb);
            #pragma unroll
            for (int bj = 0; bj < 2; bj++) {
                uint32_t bf[4];
                LDSM_X4(bf, sb + OF_B + boffs[bj] + kb);
                #pragma unroll
                for (int mi = 0; mi < 2; mi++) {
                    mma_fp16(acc[mi][bj * 2 + 0], ah[mi], bf[0], bf[2]);
                    mma_fp16(acc[mi][bj * 2 + 1], ah[mi], bf[1], bf[3]);
                }
            }
        }
    }

    // --- epilogue: warp covers rows wm*32..+31, cols wn*32..+31
    float res = resp[0];
    int rbase = n0 + wm * 32 + (lane >> 2);
    int cbase = wn * 32 + (lane & 3) * 2;
    #pragma unroll
    for (int mi = 0; mi < 2; mi++) {
        #pragma unroll
        for (int j = 0; j < 4; j++) {
            int col = cbase + j * 8;
            int nlo = rbase + mi * 16;
            int nhi = nlo + 8;
            if (nlo < N) {
                const float2 xv = *(const float2*)(x + (size_t)nlo * DD + col);
                float2 o;
                o.x = xv.x + res * tanh_fast(acc[mi][j][0]);
                o.y = xv.y + res * tanh_fast(acc[mi][j][1]);
                *(float2*)(out + (size_t)nlo * DD + col) = o;
            }
            if (nhi < N) {
                const float2 xv = *(const float2*)(x + (size_t)nhi * DD + col);
                float2 o;
                o.x = xv.x + res * tanh_fast(acc[mi][j][2]);
                o.y = xv.y + res * tanh_fast(acc[mi][j][3]);
                *(float2*)(out + (size_t)nhi * DD + col) = o;
            }
        }
    }
}

// ---------------------------------------------------------------------------
// Launch
// ---------------------------------------------------------------------------
extern "C" void kernel_launch(void* const* d_in, const int* in_sizes, int n_in,
                              void* d_out, int out_size) {
    const float* emb    = (const float*)d_in[0];
    const float* change = (const float*)d_in[1];
    const float* W1     = (const float*)d_in[2];
    const float* Wl1    = (const float*)d_in[3];
    const float* rel1   = (const float*)d_in[4];
    const float* W2     = (const float*)d_in[5];
    const float* Wl2    = (const float*)d_in[6];
    const float* rel2   = (const float*)d_in[7];
    const float* res    = (const float*)d_in[8];
    const float* jw     = (const float*)d_in[9];
    const float* ewj    = (const float*)d_in[10];
    const int*   ei     = (const int*)d_in[11];
    const int*   et     = (const int*)d_in[12];
    const int*   ej     = (const int*)d_in[13];

    int N  = in_sizes[0] / DD;       // 100000
    int E  = in_sizes[12];           // 600000
    int EJ = in_sizes[10];           // 300000

    float* out1 = (float*)d_out;
    float* out2 = out1 + (size_t)N * DD;

    float *aggbase, *h, *deg;
    __half (*B)[32768];
    cudaGetSymbolAddress((void**)&aggbase, g_agg);
    cudaGetSymbolAddress((void**)&h,   g_h);
    cudaGetSymbolAddress((void**)&deg, g_deg);
    cudaGetSymbolAddress((void**)&B,   g_B);
    float* agg0 = aggbase;
    float* agg1 = aggbase + (size_t)MAXN * DD;

    const int SMEM_C = 64 * PK * 2 + 128 * PK * 2;   // 52224 B
    cudaFuncSetAttribute(combine_hmma, cudaFuncAttributeMaxDynamicSharedMemorySize, SMEM_C);

    size_t fbytes = (size_t)N * DD * sizeof(float);
    long long swarps = (E + 3) / 4;
    long long jwarps = (EJ + 3) / 4;
    int sblocks = (int)((swarps * 32 + 255) / 256);
    int jblocks = (int)((jwarps * 32 + 255) / 256);
    int cblocks = (N + 63) / 64;

    prep_kernel<<<256, 256>>>(W1, Wl1, W2, Wl2);
    cudaMemsetAsync(aggbase, 0, 2 * fbytes, 0);          // both agg buffers at once
    cudaMemsetAsync(deg, 0, (size_t)N * sizeof(float), 0);

    // Layer 1 (degree fused into scatter)
    scatter_kernel<<<sblocks, 256>>>(emb, rel1, ei, et, E, agg0, deg);
    combine_hmma<<<cblocks, 256, SMEM_C>>>(agg0, deg, emb, B[0], res, h, N);

    // Layer 2 (writes directly into out2)
    scatter_kernel<<<sblocks, 256>>>(h, rel2, ei, et, E, agg1, nullptr);
    combine_hmma<<<cblocks, 256, SMEM_C>>>(agg1, deg, h, B[1], res, out2, N);

    // Jump diffusion accumulates into out2; change passthrough into out1
    jump_kernel<<<jblocks, 256>>>(emb, ewj, ej, jw, EJ, out2);
    cudaMemcpyAsync(out1, change, fbytes, cudaMemcpyDeviceToDevice, 0);
}

// round 17
// speedup vs baseline: 1.3660x; 1.0039x over previous
#include <cuda_runtime.h>
#include <cuda_fp16.h>
#include <cstdint>

#define DD 128
#define MAXN 100000
#define PK 136            // smem tile pitch in fp16 halves (conflict-free for ldmatrix)

// ---------------- scratch (__device__ globals; no allocs allowed) ----------------
__device__ float g_agg[2][(size_t)MAXN * DD];   // double-buffered
__device__ float g_h[(size_t)MAXN * DD];
__device__ float g_deg[MAXN];
__device__ __align__(16) __half g_x16[(size_t)MAXN * DD];   // fp16(emb)
__device__ __align__(16) __half g_h16[(size_t)MAXN * DD];   // fp16(h), from combine1
__device__ __align__(16) __half g_rel16[2][200 * DD];
// fp16 images of B = [W;Wloop]^T, row-major [n=128][k=256], one per layer.
__device__ __align__(16) __half g_B[2][32768];

__device__ __forceinline__ uint32_t smem_u32(const void* p) {
    uint32_t a;
    asm("{ .reg .u64 t; cvta.to.shared.u64 t, %1; cvt.u32.u64 %0, t; }" : "=r"(a) : "l"(p));
    return a;
}
__device__ __forceinline__ float tanh_fast(float v) {
    float r;
    asm("tanh.approx.f32 %0, %1;" : "=f"(r) : "f"(v));
    return r;
}
__device__ __forceinline__ float4 h4_to_f4(uint2 u) {
    __half2 a = *(__half2*)&u.x, b = *(__half2*)&u.y;
    float2 fa = __half22float2(a), fb = __half22float2(b);
    return make_float4(fa.x, fa.y, fb.x, fb.y);
}
#define LDSM_X4(R, addr) \
    asm volatile("ldmatrix.sync.aligned.m8n8.x4.shared.b16 {%0,%1,%2,%3}, [%4];" \
        : "=r"((R)[0]), "=r"((R)[1]), "=r"((R)[2]), "=r"((R)[3]) : "r"(addr))

__device__ __forceinline__ void mma_fp16(float* c, const uint32_t* a, uint32_t b0, uint32_t b1) {
    asm volatile(
        "mma.sync.aligned.m16n8k16.row.col.f32.f16.f16.f32 "
        "{%0,%1,%2,%3}, {%4,%5,%6,%7}, {%8,%9}, {%0,%1,%2,%3};"
        : "+f"(c[0]), "+f"(c[1]), "+f"(c[2]), "+f"(c[3])
        : "r"(a[0]), "r"(a[1]), "r"(a[2]), "r"(a[3]), "r"(b0), "r"(b1));
}

// ---------------------------------------------------------------------------
// Prep B: B[n][k] = (k<128 ? W[k][n] : Wl[k-128][n]); fp16, row-major.
// ---------------------------------------------------------------------------
__global__ void prep_kernel(const float* __restrict__ W1, const float* __restrict__ Wl1,
                            const float* __restrict__ W2, const float* __restrict__ Wl2) {
    int idx = blockIdx.x * blockDim.x + threadIdx.x;   // 0..65535
    int l = idx >> 15;
    int n = (idx >> 8) & 127;
    int k = idx & 255;
    const float* W  = l ? W2  : W1;
    const float* Wl = l ? Wl2 : Wl1;
    float v = (k < 128) ? W[k * 128 + n] : Wl[(k - 128) * 128 + n];
    g_B[l][n * 256 + k] = __float2half_rn(v);
}

// ---------------------------------------------------------------------------
// Prep fp16 gather images: emb16, rel116, rel216 (float4 -> half4 units).
// ---------------------------------------------------------------------------
__global__ void prep16_kernel(const float* __restrict__ emb,
                              const float* __restrict__ rel1, const float* __restrict__ rel2,
                              int N, int R,
                              __half* __restrict__ emb16,
                              __half* __restrict__ rel116, __half* __restrict__ rel216) {
    int i = blockIdx.x * blockDim.x + threadIdx.x;
    int nemb = N * 32, nrel = R * 32;
    const float4* src;
    __half* dst;
    int j;
    if (i < nemb)                  { src = (const float4*)emb;  dst = emb16;  j = i; }
    else if (i < nemb + nrel)      { src = (const float4*)rel1; dst = rel116; j = i - nemb; }
    else if (i < nemb + 2 * nrel)  { src = (const float4*)rel2; dst = rel216; j = i - nemb - nrel; }
    else return;
    float4 v = __ldg(src + j);
    __half2 p0 = __floats2half2_rn(v.x, v.y), p1 = __floats2half2_rn(v.z, v.w);
    ((uint2*)dst)[j] = make_uint2(*(unsigned*)&p0, *(unsigned*)&p1);
}

// ---------------------------------------------------------------------------
// Zero: agg (both buffers) + deg, uint4 grid-stride.
// ---------------------------------------------------------------------------
__global__ void zero_kernel(uint4* __restrict__ agg, int n4agg,
                            uint4* __restrict__ deg, int n4deg) {
    int i = blockIdx.x * blockDim.x + threadIdx.x;
    int stride = gridDim.x * blockDim.x;
    uint4 z = make_uint4(0, 0, 0, 0);
    for (int j = i; j < n4agg; j += stride) agg[j] = z;
    for (int j = i; j < n4deg; j += stride) deg[j] = z;
}

// ---------------------------------------------------------------------------
// Scatter: agg[dst] += fp32(x16[src]) * fp32(rel16[type]); 4 edges/warp.
// fp16 gathers halve L2 read traffic; math + RED stay fp32.
// ---------------------------------------------------------------------------
__global__ void scatter_kernel(const __half* __restrict__ x16, const __half* __restrict__ rel16,
                               const int* __restrict__ ei, const int* __restrict__ et,
                               int E, float* __restrict__ agg, float* __restrict__ deg) {
    int gw   = (blockIdx.x * blockDim.x + threadIdx.x) >> 5;
    int lane = threadIdx.x & 31;
    int e0 = gw * 4;
    if (e0 >= E) return;
    int   sidx[4], didx[4], tidx[4];
    bool  ok[4];
    #pragma unroll
    for (int q = 0; q < 4; q++) {
        int e = e0 + q;
        ok[q] = e < E;
        int es = ok[q] ? e : e0;
        sidx[q] = __ldg(ei + es);
        didx[q] = __ldg(ei + E + es);
        tidx[q] = __ldg(et + es);
    }
    uint2 xu[4], ru[4];
    #pragma unroll
    for (int q = 0; q < 4; q++) {
        xu[q] = ((const uint2*)(x16 + (size_t)sidx[q] * DD))[lane];
        ru[q] = __ldg(((const uint2*)(rel16 + (size_t)tidx[q] * DD)) + lane);
    }
    #pragma unroll
    for (int q = 0; q < 4; q++) {
        if (ok[q]) {
            float4 xv = h4_to_f4(xu[q]);
            float4 rv = h4_to_f4(ru[q]);
            float4 m = make_float4(xv.x * rv.x, xv.y * rv.y, xv.z * rv.z, xv.w * rv.w);
            atomicAdd((float4*)(agg + (size_t)didx[q] * DD + lane * 4), m);
        }
    }
    if (deg != nullptr && lane == 0) {
        #pragma unroll
        for (int q = 0; q < 4; q++)
            if (ok[q]) atomicAdd(deg + didx[q], 1.0f);
    }
}

// ---------------------------------------------------------------------------
// Jump: out[jdst] += jump_weight * edge_w * fp32(emb16[jsrc]); 4 edges/warp.
// ---------------------------------------------------------------------------
__global__ void jump_kernel(const __half* __restrict__ emb16, const float* __restrict__ ew,
                            const int* __restrict__ ej, const float* __restrict__ jw,
                            int EJ, float* __restrict__ out) {
    int gw   = (blockIdx.x * blockDim.x + threadIdx.x) >> 5;
    int lane = threadIdx.x & 31;
    int e0 = gw * 4;
    if (e0 >= EJ) return;
    float jwv = jw[0];
    int  sidx[4], didx[4];
    bool ok[4];
    float wq[4];
    #pragma unroll
    for (int q = 0; q < 4; q++) {
        int e = e0 + q;
        ok[q] = e < EJ;
        int es = ok[q] ? e : e0;
        sidx[q] = __ldg(ej + es);
        didx[q] = __ldg(ej + EJ + es);
        wq[q]   = jwv * __ldg(ew + es);
    }
    uint2 xu[4];
    #pragma unroll
    for (int q = 0; q < 4; q++)
        xu[q] = ((const uint2*)(emb16 + (size_t)sidx[q] * DD))[lane];
    #pragma unroll
    for (int q = 0; q < 4; q++) {
        if (ok[q]) {
            float4 xv = h4_to_f4(xu[q]);
            float4 m = make_float4(wq[q] * xv.x, wq[q] * xv.y, wq[q] * xv.z, wq[q] * xv.w);
            atomicAdd((float4*)(out + (size_t)didx[q] * DD + lane * 4), m);
        }
    }
}

// ---------------------------------------------------------------------------
// Combine (fp16 HMMA): out[n] = x[n] + res*tanh([agg/deg | x] @ [W;Wl])
// CTA: 64 nodes x 128 outs, K=256 in two 128-halves. 8 warps as 2(M) x 4(N).
// Optionally writes fp16 copy of out (h16) for the next scatter's gathers.
// smem: A (17KB) + B (35KB) = 52KB -> 3 CTAs/SM.
// ---------------------------------------------------------------------------
__global__ void __launch_bounds__(256, 3) combine_hmma(
    const float* __restrict__ agg, const float* __restrict__ deg,
    const float* __restrict__ x,
    const __half* __restrict__ Bimg,
    const float* __restrict__ resp, float* __restrict__ out,
    __half* __restrict__ h16out, int N)
{
    extern __shared__ char smem[];
    const int TILE_A = 64 * PK * 2;                  // 17408 B
    const int OF_A = 0, OF_B = TILE_A;
    const uint32_t sb = smem_u32(smem);

    int tid = threadIdx.x, wid = tid >> 5, lane = tid & 31;
    int n0 = blockIdx.x * 64;
    int wn = wid & 3, wm = wid >> 2;                 // 4 N-groups x 2 M-groups

    int lrow = (lane & 7) + ((lane >> 3) & 1) * 8;
    int lcol = ((lane >> 4) & 1) * 8;

    uint32_t aoffs[2], boffs[2];
    #pragma unroll
    for (int mi = 0; mi < 2; mi++)
        aoffs[mi] = (uint32_t)(((wm * 32 + mi * 16 + lrow) * PK + lcol) * 2);
    #pragma unroll
    for (int bj = 0; bj < 2; bj++)
        boffs[bj] = (uint32_t)(((wn * 32 + bj * 16 + lrow) * PK + lcol) * 2);

    float acc[2][4][4];
    #pragma unroll
    for (int mi = 0; mi < 2; mi++)
        #pragma unroll
        for (int j = 0; j < 4; j++)
            #pragma unroll
            for (int q = 0; q < 4; q++) acc[mi][j][q] = 0.0f;

    for (int half = 0; half < 2; half++) {
        if (half) __syncthreads();

        // --- A half: 64 rows x 128-k slice (agg/deg or x) -> fp16
        const float* src = half ? x : agg;
        for (int i = tid; i < 64 * 32; i += 256) {
            int row = i >> 5, c4 = i & 31, node = n0 + row;
            float4 v = make_float4(0, 0, 0, 0);
            if (node < N) {
                v = ((const float4*)(src + (size_t)node * DD))[c4];
                if (half == 0) {
                    float sc = 1.0f / fmaxf(deg[node], 1.0f);
                    v.x *= sc; v.y *= sc; v.z *= sc; v.w *= sc;
                }
            }
            __half2 p0 = __floats2half2_rn(v.x, v.y);
            __half2 p1 = __floats2half2_rn(v.z, v.w);
            unsigned long long hp =
                (unsigned long long)(*(const unsigned*)&p0) |
                ((unsigned long long)(*(const unsigned*)&p1) << 32);
            *(unsigned long long*)(smem + OF_A + (size_t)(row * PK + c4 * 4) * 2) = hp;
        }
        // --- B half: [128 n][128 k-slice] from prebuilt image (pure copy)
        const uint4* bi = (const uint4*)(Bimg + half * 128);
        for (int i = tid; i < 128 * 16; i += 256) {
            int row = i >> 4, c = i & 15;
            uint4 vh = bi[row * 32 + c];
            *(uint4*)(smem + OF_B + (size_t)row * PK * 2 + (size_t)c * 16) = vh;
        }
        __syncthreads();

        // --- MMA over 8 k16 steps
        #pragma unroll
        for (int s = 0; s < 8; s++) {
            uint32_t kb = (uint32_t)s * 32;
            uint32_t ah[2][4];
            #pragma unroll
            for (int mi = 0; mi < 2; mi++)
                LDSM_X4(ah[mi], sb + OF_A + aoffs[mi] + kb);
            #pragma unroll
            for (int bj = 0; bj < 2; bj++) {
                uint32_t bf[4];
                LDSM_X4(bf, sb + OF_B + boffs[bj] + kb);
                #pragma unroll
                for (int mi = 0; mi < 2; mi++) {
                    mma_fp16(acc[mi][bj * 2 + 0], ah[mi], bf[0], bf[2]);
                    mma_fp16(acc[mi][bj * 2 + 1], ah[mi], bf[1], bf[3]);
                }
            }
        }
    }

    // --- epilogue: warp covers rows wm*32..+31, cols wn*32..+31
    float res = resp[0];
    int rbase = n0 + wm * 32 + (lane >> 2);
    int cbase = wn * 32 + (lane & 3) * 2;
    #pragma unroll
    for (int mi = 0; mi < 2; mi++) {
        #pragma unroll
        for (int j = 0; j < 4; j++) {
            int col = cbase + j * 8;
            int nlo = rbase + mi * 16;
            int nhi = nlo + 8;
            if (nlo < N) {
                const float2 xv = *(const float2*)(x + (size_t)nlo * DD + col);
                float2 o;
                o.x = xv.x + res * tanh_fast(acc[mi][j][0]);
                o.y = xv.y + res * tanh_fast(acc[mi][j][1]);
                *(float2*)(out + (size_t)nlo * DD + col) = o;
                if (h16out) {
                    __half2 p = __floats2half2_rn(o.x, o.y);
                    *(unsigned*)(h16out + (size_t)nlo * DD + col) = *(unsigned*)&p;
                }
            }
            if (nhi < N) {
                const float2 xv = *(const float2*)(x + (size_t)nhi * DD + col);
                float2 o;
                o.x = xv.x + res * tanh_fast(acc[mi][j][2]);
                o.y = xv.y + res * tanh_fast(acc[mi][j][3]);
                *(float2*)(out + (size_t)nhi * DD + col) = o;
                if (h16out) {
                    __half2 p = __floats2half2_rn(o.x, o.y);
                    *(unsigned*)(h16out + (size_t)nhi * DD + col) = *(unsigned*)&p;
                }
            }
        }
    }
}

// ---------------------------------------------------------------------------
// Launch
// ---------------------------------------------------------------------------
extern "C" void kernel_launch(void* const* d_in, const int* in_sizes, int n_in,
                              void* d_out, int out_size) {
    const float* emb    = (const float*)d_in[0];
    const float* change = (const float*)d_in[1];
    const float* W1     = (const float*)d_in[2];
    const float* Wl1    = (const float*)d_in[3];
    const float* rel1   = (const float*)d_in[4];
    const float* W2     = (const float*)d_in[5];
    const float* Wl2    = (const float*)d_in[6];
    const float* rel2   = (const float*)d_in[7];
    const float* res    = (const float*)d_in[8];
    const float* jw     = (const float*)d_in[9];
    const float* ewj    = (const float*)d_in[10];
    const int*   ei     = (const int*)d_in[11];
    const int*   et     = (const int*)d_in[12];
    const int*   ej     = (const int*)d_in[13];

    int N  = in_sizes[0] / DD;       // 100000
    int R  = in_sizes[4] / DD;       // 200
    int E  = in_sizes[12];           // 600000
    int EJ = in_sizes[10];           // 300000

    float* out1 = (float*)d_out;
    float* out2 = out1 + (size_t)N * DD;

    float *aggbase, *h, *deg;
    __half *x16, *h16;
    __half (*rel16)[200 * DD];
    __half (*B)[32768];
    cudaGetSymbolAddress((void**)&aggbase, g_agg);
    cudaGetSymbolAddress((void**)&h,     g_h);
    cudaGetSymbolAddress((void**)&deg,   g_deg);
    cudaGetSymbolAddress((void**)&x16,   g_x16);
    cudaGetSymbolAddress((void**)&h16,   g_h16);
    cudaGetSymbolAddress((void**)&rel16, g_rel16);
    cudaGetSymbolAddress((void**)&B,     g_B);
    float* agg0 = aggbase;
    float* agg1 = aggbase + (size_t)MAXN * DD;

    const int SMEM_C = 64 * PK * 2 + 128 * PK * 2;   // 52224 B
    cudaFuncSetAttribute(combine_hmma, cudaFuncAttributeMaxDynamicSharedMemorySize, SMEM_C);

    size_t fbytes = (size_t)N * DD * sizeof(float);
    long long swarps = (E + 3) / 4;
    long long jwarps = (EJ + 3) / 4;
    int sblocks = (int)((swarps * 32 + 255) / 256);
    int jblocks = (int)((jwarps * 32 + 255) / 256);
    int cblocks = (N + 63) / 64;
    int pblocks = (N * 32 + R * 64 + 255) / 256;

    prep_kernel<<<256, 256>>>(W1, Wl1, W2, Wl2);
    prep16_kernel<<<pblocks, 256>>>(emb, rel1, rel2, N, R, x16, rel16[0], rel16[1]);
    int n4agg = 2 * MAXN * DD / 4;
    int n4deg = MAXN / 4;
    zero_kernel<<<4096, 256>>>((uint4*)aggbase, n4agg, (uint4*)deg, n4deg);

    // Layer 1 (degree fused into scatter; h16 produced for scatter2)
    scatter_kernel<<<sblocks, 256>>>(x16, rel16[0], ei, et, E, agg0, deg);
    combine_hmma<<<cblocks, 256, SMEM_C>>>(agg0, deg, emb, B[0], res, h, h16, N);

    // Layer 2 (writes directly into out2)
    scatter_kernel<<<sblocks, 256>>>(h16, rel16[1], ei, et, E, agg1, nullptr);
    combine_hmma<<<cblocks, 256, SMEM_C>>>(agg1, deg, h, B[1], res, out2, nullptr, N);

    // Jump diffusion accumulates into out2; change passthrough into out1
    jump_kernel<<<jblocks, 256>>>(x16, ewj, ej, jw, EJ, out2);
    cudaMemcpyAsync(out1, change, fbytes, cudaMemcpyDeviceToDevice, 0);
}